// round 14
// baseline (speedup 1.0000x reference)
#include <cuda_runtime.h>
#include <cstdint>

#define T_STEPS 512
#define BATCH   32
#define DIM     2048
#define BD      (BATCH * DIM)          /* 65536 */
#define NBLK    128                    /* persistent blocks, <= 148 SMs */

// d_out layout (floats): output[512,BD] | log_h[513,BD] | sign_h[513,BD] | h_linear[512,BD]
#define O_OUT   ((size_t)0)
#define O_LOG   ((size_t)512 * BD)
#define O_SIGN  (O_LOG + (size_t)513 * BD)
#define O_HLIN  (O_SIGN + (size_t)513 * BD)

// ---------------- static device scratch ----------------
__device__ float g_hbuf[2][BD];          // h state double buffer, [j*32 + b]
__device__ float g_u[DIM];
__device__ float g_v[DIM];
__device__ float g_w[DIM];
__device__ float g_part16[16 * DIM];
__device__ float g_scale;
__device__ unsigned int g_bar_count;
__device__ volatile unsigned int g_bar_gen;

// ---------------- helpers ----------------
__device__ __forceinline__ float block_reduce_sum_1024(float v) {
    __shared__ float sred[32];
    int lane = threadIdx.x & 31, w = threadIdx.x >> 5;
#pragma unroll
    for (int o = 16; o; o >>= 1) v += __shfl_down_sync(0xffffffffu, v, o);
    if (lane == 0) sred[w] = v;
    __syncthreads();
    if (w == 0) {
        float r = sred[lane];
#pragma unroll
        for (int o = 16; o; o >>= 1) r += __shfl_down_sync(0xffffffffu, r, o);
        if (lane == 0) sred[0] = r;
    }
    __syncthreads();
    return sred[0];
}

// ---------------- spectral norm (power iteration) ----------------
__global__ void spec_init() {
    int t = threadIdx.x;
    float a0 = cosf(0.7f * (float)t + 0.3f);
    float a1 = cosf(0.7f * (float)(t + 1024) + 0.3f);
    float tot = block_reduce_sum_1024(a0 * a0 + a1 * a1);
    float inv = rsqrtf(tot);
    g_u[t] = a0 * inv;
    g_u[t + 1024] = a1 * inv;
}

// partial of v = W^T u. grid (8,16), block 256.
__global__ void spec_matvecT(const float* __restrict__ W) {
    __shared__ float us[128];
    int j = blockIdx.x * 256 + threadIdx.x;
    int i0 = blockIdx.y * 128;
    if (threadIdx.x < 128) us[threadIdx.x] = g_u[i0 + threadIdx.x];
    __syncthreads();
    float acc = 0.0f;
#pragma unroll 8
    for (int i = 0; i < 128; ++i)
        acc += W[(size_t)(i0 + i) * DIM + j] * us[i];
    g_part16[blockIdx.y * DIM + j] = acc;
}

__global__ void spec_reduce16_norm() {
    int t = threadIdx.x;
    float s0 = 0.0f, s1 = 0.0f;
#pragma unroll
    for (int p = 0; p < 16; ++p) {
        s0 += g_part16[p * DIM + t];
        s1 += g_part16[p * DIM + t + 1024];
    }
    float tot = block_reduce_sum_1024(s0 * s0 + s1 * s1);
    float inv = 1.0f / (sqrtf(tot) + 1e-8f);
    g_v[t] = s0 * inv;
    g_v[t + 1024] = s1 * inv;
}

// w = W v, warp-per-row. grid 256, block 256.
__global__ void spec_matvecR(const float* __restrict__ W) {
    int w = threadIdx.x >> 5, lane = threadIdx.x & 31;
    int row = blockIdx.x * 8 + w;
    const float* wr = W + (size_t)row * DIM;
    float acc = 0.0f;
#pragma unroll 4
    for (int k = lane; k < DIM; k += 32) acc += wr[k] * g_v[k];
#pragma unroll
    for (int o = 16; o; o >>= 1) acc += __shfl_down_sync(0xffffffffu, acc, o);
    if (lane == 0) g_w[row] = acc;
}

__global__ void spec_norm_u() {
    int t = threadIdx.x;
    float s0 = g_w[t], s1 = g_w[t + 1024];
    float tot = block_reduce_sum_1024(s0 * s0 + s1 * s1);
    float inv = 1.0f / (sqrtf(tot) + 1e-8f);
    g_u[t] = s0 * inv;
    g_u[t + 1024] = s1 * inv;
}

// sigma = |u . (W v)| = |u . w| ; scale = 0.9/(sigma+1e-8). Also reset barrier.
__global__ void spec_sigma() {
    int t = threadIdx.x;
    float d = g_u[t] * g_w[t] + g_u[t + 1024] * g_w[t + 1024];
    float tot = block_reduce_sum_1024(d);
    if (threadIdx.x == 0) {
        g_scale = 0.9f / (fabsf(tot) + 1e-8f);
        g_bar_count = 0;
        g_bar_gen = 0;
    }
}

// ---------------- init h0 and first log/sign rows ----------------
__global__ void init_h(const float* __restrict__ log_h0,
                       const float* __restrict__ sign_h0,
                       float* __restrict__ out) {
    int i = blockIdx.x * 1024 + threadIdx.x;   // b*DIM + j
    int b = i >> 11, j = i & 2047;
    float lh = log_h0[i];
    float sh = sign_h0[i];
    g_hbuf[0][j * 32 + b] = sh * expf(lh);     // exp(-1e30) -> 0
    out[O_LOG + i] = lh;
    out[O_SIGN + i] = sh;
}

// ---------------- feedforward SGEMM: pre & delta ----------------
// z=0: pre = X@R_x^T + b  -> O1; z=1: delta = sigmoid(X@W_delta^T + b_delta) -> O2
__global__ __launch_bounds__(256) void ffwd_gemm(
    const float* __restrict__ X,
    const float* __restrict__ W1, const float* __restrict__ b1,
    const float* __restrict__ W2, const float* __restrict__ b2,
    float* __restrict__ O1, float* __restrict__ O2) {
    __shared__ __align__(16) float As[8][132];
    __shared__ __align__(16) float Bs[8][132];

    const int z = blockIdx.z;
    const float* W = z ? W2 : W1;
    const float* bias = z ? b2 : b1;
    float* O = z ? O2 : O1;

    const int m0 = blockIdx.y * 128;
    const int n0 = blockIdx.x * 128;
    const int t = threadIdx.x;
    const int tx = t & 15, ty = t >> 4;
    const int lm = t >> 1;
    const int lk = (t & 1) * 4;

    const float* aptr = X + (size_t)(m0 + lm) * DIM + lk;
    const float* bptr = W + (size_t)(n0 + lm) * DIM + lk;

    float acc[8][8];
#pragma unroll
    for (int i = 0; i < 8; ++i)
#pragma unroll
        for (int j = 0; j < 8; ++j) acc[i][j] = 0.0f;

    float4 aN = *(const float4*)aptr;
    float4 bN = *(const float4*)bptr;

#pragma unroll 1
    for (int kt = 0; kt < DIM / 8; ++kt) {
        As[lk + 0][lm] = aN.x; As[lk + 1][lm] = aN.y;
        As[lk + 2][lm] = aN.z; As[lk + 3][lm] = aN.w;
        Bs[lk + 0][lm] = bN.x; Bs[lk + 1][lm] = bN.y;
        Bs[lk + 2][lm] = bN.z; Bs[lk + 3][lm] = bN.w;
        __syncthreads();
        if (kt + 1 < DIM / 8) {
            aN = *(const float4*)(aptr + (size_t)(kt + 1) * 8);
            bN = *(const float4*)(bptr + (size_t)(kt + 1) * 8);
        }
#pragma unroll
        for (int kk = 0; kk < 8; ++kk) {
            float4 a0 = *(const float4*)&As[kk][ty * 8];
            float4 a1 = *(const float4*)&As[kk][ty * 8 + 4];
            float4 b0 = *(const float4*)&Bs[kk][tx * 8];
            float4 b1v = *(const float4*)&Bs[kk][tx * 8 + 4];
            float av[8] = {a0.x, a0.y, a0.z, a0.w, a1.x, a1.y, a1.z, a1.w};
            float bv[8] = {b0.x, b0.y, b0.z, b0.w, b1v.x, b1v.y, b1v.z, b1v.w};
#pragma unroll
            for (int i = 0; i < 8; ++i)
#pragma unroll
                for (int j = 0; j < 8; ++j) acc[i][j] += av[i] * bv[j];
        }
        __syncthreads();
    }

    float bj[8];
#pragma unroll
    for (int j = 0; j < 8; ++j) bj[j] = bias[n0 + tx * 8 + j];

#pragma unroll
    for (int i = 0; i < 8; ++i) {
        size_t row = (size_t)(m0 + ty * 8 + i) * DIM + n0 + tx * 8;
        float v[8];
#pragma unroll
        for (int j = 0; j < 8; ++j) {
            float val = acc[i][j] + bj[j];
            if (z) val = 1.0f / (1.0f + expf(-val));
            v[j] = val;
        }
        *(float4*)&O[row]     = make_float4(v[0], v[1], v[2], v[3]);
        *(float4*)&O[row + 4] = make_float4(v[4], v[5], v[6], v[7]);
    }
}

// ---------------- persistent recurrence ----------------
// 128 blocks x 256 threads, all co-resident (1/SM). Block bid covers columns
// j in [bid*16, bid*16+16) for all 32 batches. One device-wide barrier per step.
__device__ __forceinline__ void grid_sync(unsigned int gen) {
    __syncthreads();
    if (threadIdx.x == 0) {
        __threadfence();                       // release: h_next visible in L2
        if (atomicAdd(&g_bar_count, 1) == NBLK - 1) {
            g_bar_count = 0;
            __threadfence();
            g_bar_gen = gen + 1;
        } else {
            while (g_bar_gen <= gen) { }
        }
        __threadfence();                       // acquire
    }
    __syncthreads();
}

__global__ __launch_bounds__(256) void recurrent_persist(
    const float* __restrict__ Rh, const float* __restrict__ x,
    const float* __restrict__ b_gate, float* __restrict__ out) {
    __shared__ __align__(16) float hsT[256 * 32];   // 32 KB: h chunk, [k_local*32+b]
    __shared__ float s_rec[16 * 33];
    __shared__ float s_hprev[16 * 33];
    __shared__ float s_hn[16 * 33];
    __shared__ float s_bg[16];

    const int tid = threadIdx.x;
    const int w = tid >> 5, lane = tid & 31;
    const int j0 = blockIdx.x * 16;
    const int jA = j0 + 2 * w, jB = jA + 1;
    const float scale = g_scale;
    if (tid < 16) s_bg[tid] = b_gate[j0 + tid];

    for (int t = 0; t < T_STEPS; ++t) {
        const int p = t & 1;
        const float* hb = g_hbuf[p];
        float acc0 = 0.0f, acc1 = 0.0f;

        for (int ch = 0; ch < 8; ++ch) {
            const int kb = ch * 256;
            __syncthreads();                    // hsT reuse protection
            // stage 32 KB of h (linear copy; L1-bypass: written by other SMs)
            const float4* src = (const float4*)(hb + kb * 32);
            float4* dst = (float4*)hsT;
#pragma unroll
            for (int r = 0; r < 8; ++r)
                dst[tid + r * 256] = __ldcg(src + tid + r * 256);
            __syncthreads();
            const float4* ra4 = (const float4*)(Rh + (size_t)jA * DIM + kb);
            const float4* rb4 = (const float4*)(Rh + (size_t)jB * DIM + kb);
#pragma unroll 8
            for (int q = 0; q < 64; ++q) {
                float4 ra = __ldg(ra4 + q);
                float4 rb = __ldg(rb4 + q);
                float h0v = hsT[(4 * q + 0) * 32 + lane];
                float h1v = hsT[(4 * q + 1) * 32 + lane];
                float h2v = hsT[(4 * q + 2) * 32 + lane];
                float h3v = hsT[(4 * q + 3) * 32 + lane];
                acc0 += ra.x * h0v + ra.y * h1v + ra.z * h2v + ra.w * h3v;
                acc1 += rb.x * h0v + rb.y * h1v + rb.z * h2v + rb.w * h3v;
            }
        }
        __syncthreads();
        // stash rec + h_prev (matvec layout: fixed j, lanes = b)
        s_rec[(2 * w) * 33 + lane]     = acc0 * scale;
        s_rec[(2 * w + 1) * 33 + lane] = acc1 * scale;
        s_hprev[(2 * w) * 33 + lane]     = __ldcg(hb + jA * 32 + lane);
        s_hprev[(2 * w + 1) * 33 + lane] = __ldcg(hb + jB * 32 + lane);
        __syncthreads();

        // fused finalize, remapped to (b, jl) so d_out accesses coalesce over j
#pragma unroll
        for (int e = 0; e < 2; ++e) {
            int idx = tid + e * 256;            // [0,512) = 32 b x 16 jl
            int jl = idx & 15, b = idx >> 4;
            int j = j0 + jl;
            size_t tb = (size_t)t * BD + (size_t)b * DIM + j;
            float rec   = s_rec[jl * 33 + b];
            float hp    = s_hprev[jl * 33 + b];
            float pre   = out[O_HLIN + tb];     // stashed pre-activation
            float delta = out[O_OUT + tb];      // stashed sigmoid(delta)
            float cand = tanhf(pre + rec);
            float hn = (1.0f - delta) * hp + delta * cand;
            float ln = logf(fmaxf(fabsf(hn), 1e-30f));
            float sn = hn >= 0.0f ? 1.0f : -1.0f;
            float zg = hn + x[tb] + s_bg[jl];
            float gate = zg / (1.0f + expf(-zg));
            out[O_OUT + tb]       = hn * gate;  // output (overwrites delta slot)
            out[O_LOG + tb + BD]  = ln;         // log_h[t+1]
            out[O_SIGN + tb + BD] = sn;         // sign_h[t+1]
            out[O_HLIN + tb]      = hn;         // h_linear (overwrites pre slot)
            s_hn[jl * 33 + b] = sn * expf(ln);  // exact log/exp round-trip
        }
        __syncthreads();
        // write next h state in [j][b] layout (coalesced), L2-only
        float* hnext = g_hbuf[1 - p];
        __stcg(hnext + jA * 32 + lane, s_hn[(2 * w) * 33 + lane]);
        __stcg(hnext + jB * 32 + lane, s_hn[(2 * w + 1) * 33 + lane]);

        grid_sync((unsigned int)t);
    }
}

// ---------------- launch ----------------
extern "C" void kernel_launch(void* const* d_in, const int* in_sizes, int n_in,
                              void* d_out, int out_size) {
    const float* x       = (const float*)d_in[0];
    const float* log_h0  = (const float*)d_in[1];
    const float* sign_h0 = (const float*)d_in[2];
    const float* R_h     = (const float*)d_in[3];
    const float* R_x     = (const float*)d_in[4];
    const float* W_delta = (const float*)d_in[5];
    const float* b       = (const float*)d_in[6];
    const float* b_delta = (const float*)d_in[7];
    const float* b_gate  = (const float*)d_in[8];
    float* out = (float*)d_out;

    // 1) spectral norm scale (also resets the grid barrier)
    spec_init<<<1, 1024>>>();
    for (int it = 0; it < 3; ++it) {
        spec_matvecT<<<dim3(8, 16), 256>>>(R_h);
        spec_reduce16_norm<<<1, 1024>>>();
        spec_matvecR<<<256, 256>>>(R_h);
        spec_norm_u<<<1, 1024>>>();
    }
    spec_sigma<<<1, 1024>>>();

    // 2) h0 + first log/sign rows
    init_h<<<64, 1024>>>(log_h0, sign_h0, out);

    // 3) time-parallel feedforward: pre -> h_linear region, delta -> output region
    ffwd_gemm<<<dim3(DIM / 128, (T_STEPS * BATCH) / 128, 2), 256>>>(
        x, R_x, b, W_delta, b_delta, out + O_HLIN, out + O_OUT);

    // 4) sequential recurrence: ONE persistent kernel (graph stays tiny)
    recurrent_persist<<<NBLK, 256>>>(R_h, x, b_gate, out);
}